// round 4
// baseline (speedup 1.0000x reference)
#include <cuda_runtime.h>
#include <cuda_bf16.h>

#define SEQ   4096
#define EMBED 256
#define NQ    8
#define TAGS  50
#define DIN   264   // EMBED + NQ
#define TCHUNK 8    // timesteps per precompute block

// Scratch (device globals — no dynamic allocation allowed)
__device__ float g_ax[(SEQ + 8) * 32];  // [t][gate][q] pre-activations (+pad for prefetch)
__device__ float g_h[SEQ * NQ];         // lstm hidden outputs

// ---------------------------------------------------------------------------
// Kernel 1: ax[t][g][q] = W_g[q, :256] @ emb[sentence[t]] + b_g[q]
// 512 blocks x 8 timesteps. Weights in registers (32/thread), embedding row
// double-buffered in padded (conflict-free) smem. 8 threads per (g,q) output.
// ---------------------------------------------------------------------------
__global__ void __launch_bounds__(256) precompute_kernel(
        const int* __restrict__ sent, const float* __restrict__ emb,
        const float* __restrict__ Wf, const float* __restrict__ bf,
        const float* __restrict__ Wi, const float* __restrict__ bi,
        const float* __restrict__ Wu, const float* __restrict__ bu,
        const float* __restrict__ Wo, const float* __restrict__ bo) {
    __shared__ float xe[2][264];               // 256 elems padded: idx + (idx>>5)

    const int tid  = threadIdx.x;
    const int t0   = blockIdx.x * TCHUNK;
    const int outi = tid >> 3;                 // 0..31 : gate*8 + q
    const int g    = outi >> 3;
    const int q    = outi & 7;
    const int sub  = tid & 7;

    const float* W = (g == 0) ? Wf : (g == 1) ? Wi : (g == 2) ? Wu : Wo;
    const float* b = (g == 0) ? bf : (g == 1) ? bi : (g == 2) ? bu : bo;

    // weights for my 32-element slice of the dot product -> registers
    float wreg[32];
    const float* row = W + q * DIN + sub * 32;
#pragma unroll
    for (int j = 0; j < 32; j++) wreg[j] = row[j];
    const float bias = b[q];

    // preload first embedding row
    {
        const int s = sent[t0];
        xe[0][tid + (tid >> 5)] = emb[(size_t)s * EMBED + tid];
    }
    __syncthreads();

    const int pbase = sub * 33;                // padded base for reads

#pragma unroll
    for (int i = 0; i < TCHUNK; i++) {
        const int buf = i & 1;
        const int t   = t0 + i;

        float nxt = 0.f;
        if (i + 1 < TCHUNK) {
            const int s2 = sent[t + 1];
            nxt = emb[(size_t)s2 * EMBED + tid];
        }

        float acc = 0.f;
#pragma unroll
        for (int j = 0; j < 32; j++)
            acc = fmaf(wreg[j], xe[buf][pbase + j], acc);

        acc += __shfl_xor_sync(0xffffffffu, acc, 4);
        acc += __shfl_xor_sync(0xffffffffu, acc, 2);
        acc += __shfl_xor_sync(0xffffffffu, acc, 1);

        if (sub == 0)
            g_ax[t * 32 + outi] = acc + bias;

        if (i + 1 < TCHUNK)
            xe[buf ^ 1][tid + (tid >> 5)] = nxt;
        __syncthreads();
    }
}

// ---------------------------------------------------------------------------
// Kernel 2: sequential LSTM scan. Single warp. lane = gate*8 + q.
// Quantum layer collapses analytically:
//   z_j = prod_{k<=j} cos^2(a_k)  (j>=1);   z_0 = prod_{k=1..7} cos^2(a_k)
// Gate activations: act = C + p*B(p^2), division-free odd polynomial.
//   sigmoid (p in [0,1]): Taylor of 0.5+0.5*tanh(p/2), err ~2e-6
//   tanh    (p in [0,1]): deg-4 interpolation of tanh(sqrt(u))/sqrt(u), err ~7e-5
// Output tanh(cx) keeps Pade(9) rational (cx in [0,2.08]).
// ---------------------------------------------------------------------------
__global__ void __launch_bounds__(32, 1) scan_kernel(
        const float* __restrict__ Wf, const float* __restrict__ Wi,
        const float* __restrict__ Wu, const float* __restrict__ Wo) {
    const unsigned FULL = 0xffffffffu;
    const int lane = threadIdx.x;          // 0..31
    const int g = lane >> 3, q = lane & 7;
    const int base = g << 3;

    const float* W = (g == 0) ? Wf : (g == 1) ? Wi : (g == 2) ? Wu : Wo;
    float w[NQ];
#pragma unroll
    for (int k = 0; k < NQ; k++)
        w[k] = W[q * DIN + EMBED + k];     // recurrent slice W[:, 256:264]

    // per-lane activation polynomial: act = C + p*(b0 + b1 u + b2 u^2 + b3 u^3 + b4 u^4)
    float C, b0, b1, b2, b3, b4;
    if (g == 2) {  // tanh gate
        C  = 0.0f;
        b0 = 1.0f;
        b1 = -0.33325783f;
        b2 =  0.13215491f;
        b3 = -0.04825764f;
        b4 =  0.01095456f;
    } else {       // sigmoid gates
        C  = 0.5f;
        b0 =  0.25f;
        b1 = -0.020833333f;       // -1/48
        b2 =  0.0020833333f;      //  1/480
        b3 = -2.1081349e-4f;      // -17/80640
        b4 =  2.1356855e-5f;      //  31/1451520
    }

    bool inc[NQ];
#pragma unroll
    for (int k = 0; k < NQ; k++)
        inc[k] = (k == 0) ? (q != 0) : ((q == 0) || (k <= q));

    float hx = 0.f, cx = 0.f;

    // 4-deep prefetch ring (g_ax is padded, t+4 reads are safe)
    float ar[4];
#pragma unroll
    for (int j = 0; j < 4; j++)
        ar[j] = g_ax[j * 32 + lane];

#pragma unroll 4
    for (int t = 0; t < SEQ; t++) {
        const int r = t & 3;
        const float a = ar[r];
        ar[r] = g_ax[(t + 4) * 32 + lane];

        // ---- stage A: broadcast hx, recurrent matvec ----
        const float h0 = __shfl_sync(FULL, hx, 0);
        const float h1 = __shfl_sync(FULL, hx, 1);
        const float h2 = __shfl_sync(FULL, hx, 2);
        const float h3 = __shfl_sync(FULL, hx, 3);
        const float h4 = __shfl_sync(FULL, hx, 4);
        const float h5 = __shfl_sync(FULL, hx, 5);
        const float h6 = __shfl_sync(FULL, hx, 6);
        const float h7 = __shfl_sync(FULL, hx, 7);

        float c0 = fmaf(w[1], h1, fmaf(w[0], h0, a));
        float c1 = fmaf(w[3], h3, w[2] * h2);
        float c2 = fmaf(w[5], h5, w[4] * h4);
        float c3 = fmaf(w[7], h7, w[6] * h6);
        const float ang = (c0 + c1) + (c2 + c3);

        float cc = __cosf(ang);
        cc = cc * cc;

        // ---- stage B: gather cos^2, masked product ----
        float m[NQ];
#pragma unroll
        for (int k = 0; k < NQ; k++) {
            const float v = __shfl_sync(FULL, cc, base + k);
            m[k] = inc[k] ? v : 1.0f;
        }
        const float p = ((m[0] * m[1]) * (m[2] * m[3])) *
                        ((m[4] * m[5]) * (m[6] * m[7]));

        // ---- activation: division-free odd polynomial ----
        const float u = p * p;
        const float B = fmaf(fmaf(fmaf(fmaf(b4, u, b3), u, b2), u, b1), u, b0);
        const float act = fmaf(p, B, C);

        // ---- stage C: gather f,i,g,o for my wire ----
        const float fg = __shfl_sync(FULL, act, q);
        const float ig = __shfl_sync(FULL, act, 8 + q);
        const float gg = __shfl_sync(FULL, act, 16 + q);
        const float og = __shfl_sync(FULL, act, 24 + q);

        cx = fmaf(fg, cx, ig * gg);

        // hx = og * tanh(cx) via Pade: (og*cx*numc) * rcp(denc)
        const float tc   = cx * cx;
        const float numc = fmaf(tc + 105.f, tc, 945.f);
        const float denc = fmaf(fmaf(15.f, tc, 420.f), tc, 945.f);
        const float ocn  = (og * cx) * numc;
        hx = ocn * __fdividef(1.0f, denc);

        if (lane < NQ)
            g_h[t * NQ + lane] = hx;
    }
}

// ---------------------------------------------------------------------------
// Kernel 3: logits = h @ Wt^T + bt, then log_softmax over 50 tags.
// One block (32 threads) per timestep; lane handles tags {lane, lane+32}.
// ---------------------------------------------------------------------------
__global__ void logits_kernel(const float* __restrict__ Wt, const float* __restrict__ bt,
                              float* __restrict__ out) {
    const unsigned FULL = 0xffffffffu;
    const int t = blockIdx.x;
    const int lane = threadIdx.x;

    float h[NQ];
#pragma unroll
    for (int k = 0; k < NQ; k++)
        h[k] = g_h[t * NQ + k];

    float l0 = bt[lane];
#pragma unroll
    for (int k = 0; k < NQ; k++)
        l0 = fmaf(Wt[lane * NQ + k], h[k], l0);

    const int tag1 = lane + 32;
    const bool v1 = (tag1 < TAGS);
    float l1 = -3.0e38f;
    if (v1) {
        l1 = bt[tag1];
#pragma unroll
        for (int k = 0; k < NQ; k++)
            l1 = fmaf(Wt[tag1 * NQ + k], h[k], l1);
    }

    float mx = fmaxf(l0, l1);
#pragma unroll
    for (int d = 16; d; d >>= 1)
        mx = fmaxf(mx, __shfl_xor_sync(FULL, mx, d));

    float se = expf(l0 - mx) + (v1 ? expf(l1 - mx) : 0.f);
#pragma unroll
    for (int d = 16; d; d >>= 1)
        se += __shfl_xor_sync(FULL, se, d);

    const float ls = mx + logf(se);
    out[t * TAGS + lane] = l0 - ls;
    if (v1)
        out[t * TAGS + tag1] = l1 - ls;
}

// ---------------------------------------------------------------------------
extern "C" void kernel_launch(void* const* d_in, const int* in_sizes, int n_in,
                              void* d_out, int out_size) {
    const int*   sent = (const int*)  d_in[0];
    const float* emb  = (const float*)d_in[1];
    const float* Wf   = (const float*)d_in[2];
    const float* bf   = (const float*)d_in[3];
    const float* Wi   = (const float*)d_in[4];
    const float* bi   = (const float*)d_in[5];
    const float* Wu   = (const float*)d_in[6];
    const float* bu   = (const float*)d_in[7];
    const float* Wo   = (const float*)d_in[8];
    const float* bo   = (const float*)d_in[9];
    const float* Wt   = (const float*)d_in[10];
    const float* bt   = (const float*)d_in[11];
    float* out = (float*)d_out;

    precompute_kernel<<<SEQ / TCHUNK, 256>>>(sent, emb, Wf, bf, Wi, bi, Wu, bu, Wo, bo);
    scan_kernel<<<1, 32>>>(Wf, Wi, Wu, Wo);
    logits_kernel<<<SEQ, 32>>>(Wt, bt, out);
}

// round 5
// speedup vs baseline: 1.2775x; 1.2775x over previous
#include <cuda_runtime.h>
#include <cuda_bf16.h>

#define SEQ   4096
#define EMBED 256
#define NQ    8
#define TAGS  50
#define DIN   264   // EMBED + NQ
#define TCHUNK 16   // timesteps per precompute block

// Scratch (device globals — no dynamic allocation allowed)
__device__ float g_ax[SEQ * 32];   // [t][gate][q] pre-activations from x_t (+bias)
__device__ float g_h[SEQ * NQ];    // lstm hidden outputs

// ---------------------------------------------------------------------------
// Kernel 1: ax[t][g][q] = W_g[q, :256] @ emb[sentence[t]] + b_g[q]
// 256 blocks x 16 timesteps. Weights in registers (32/thread), embedding row
// double-buffered in padded (conflict-free) smem. 8 threads per (g,q) output.
// ---------------------------------------------------------------------------
__global__ void __launch_bounds__(256) precompute_kernel(
        const int* __restrict__ sent, const float* __restrict__ emb,
        const float* __restrict__ Wf, const float* __restrict__ bf,
        const float* __restrict__ Wi, const float* __restrict__ bi,
        const float* __restrict__ Wu, const float* __restrict__ bu,
        const float* __restrict__ Wo, const float* __restrict__ bo) {
    __shared__ float xe[2][264];               // 256 elems padded: idx + (idx>>5)

    const int tid  = threadIdx.x;
    const int t0   = blockIdx.x * TCHUNK;
    const int outi = tid >> 3;                 // 0..31 : gate*8 + q
    const int g    = outi >> 3;
    const int q    = outi & 7;
    const int sub  = tid & 7;

    const float* W = (g == 0) ? Wf : (g == 1) ? Wi : (g == 2) ? Wu : Wo;
    const float* b = (g == 0) ? bf : (g == 1) ? bi : (g == 2) ? bu : bo;

    // weights for my 32-element slice of the dot product -> registers
    float wreg[32];
    const float* row = W + q * DIN + sub * 32;
#pragma unroll
    for (int j = 0; j < 32; j++) wreg[j] = row[j];
    const float bias = b[q];

    // preload first embedding row
    {
        const int s = sent[t0];
        xe[0][tid + (tid >> 5)] = emb[(size_t)s * EMBED + tid];
    }
    __syncthreads();

    const int pbase = sub * 33;                // padded base for reads

    for (int i = 0; i < TCHUNK; i++) {
        const int buf = i & 1;
        const int t   = t0 + i;

        float nxt = 0.f;
        if (i + 1 < TCHUNK) {
            const int s2 = sent[t + 1];
            nxt = emb[(size_t)s2 * EMBED + tid];
        }

        float acc = 0.f;
#pragma unroll
        for (int j = 0; j < 32; j++)
            acc = fmaf(wreg[j], xe[buf][pbase + j], acc);

        acc += __shfl_xor_sync(0xffffffffu, acc, 4);
        acc += __shfl_xor_sync(0xffffffffu, acc, 2);
        acc += __shfl_xor_sync(0xffffffffu, acc, 1);

        if (sub == 0)
            g_ax[t * 32 + outi] = acc + bias;

        if (i + 1 < TCHUNK)
            xe[buf ^ 1][tid + (tid >> 5)] = nxt;
        __syncthreads();
    }
}

// ---------------------------------------------------------------------------
// Kernel 2: the sequential LSTM scan. Single warp. lane = gate*8 + q.
// Quantum layer collapses analytically:
//   z_j = prod_{k<=j} cos^2(a_k)  (j>=1);   z_0 = prod_{k=1..7} cos^2(a_k)
// Gate activations: act = C + p*B(p^2), division-free odd polynomial (p in [0,1]).
//   sigmoid: Taylor of 0.5+0.5*tanh(p/2), err ~2e-6
//   tanh:    deg-4-in-u interpolation of tanh(sqrt(u))/sqrt(u), err ~7e-5
// Output tanh(cx) keeps Pade(9) rational (cx in [-2.1, 2.1]).
// ---------------------------------------------------------------------------
__global__ void __launch_bounds__(32, 1) scan_kernel(
        const float* __restrict__ Wf, const float* __restrict__ Wi,
        const float* __restrict__ Wu, const float* __restrict__ Wo) {
    const unsigned FULL = 0xffffffffu;
    const int lane = threadIdx.x;          // 0..31
    const int g = lane >> 3, q = lane & 7;
    const int base = g << 3;

    const float* W = (g == 0) ? Wf : (g == 1) ? Wi : (g == 2) ? Wu : Wo;
    float w[NQ];
#pragma unroll
    for (int k = 0; k < NQ; k++)
        w[k] = W[q * DIN + EMBED + k];     // recurrent slice W[:, 256:264]

    // per-lane activation polynomial: act = C + p*(b0 + b1 u + b2 u^2 + b3 u^3 + b4 u^4)
    float C, b0, b1, b2, b3, b4;
    if (g == 2) {  // tanh gate
        C  = 0.0f;
        b0 = 1.0f;
        b1 = -0.33325783f;
        b2 =  0.13215491f;
        b3 = -0.04825764f;
        b4 =  0.01095456f;
    } else {       // sigmoid gates
        C  = 0.5f;
        b0 =  0.25f;
        b1 = -0.020833333f;       // -1/48
        b2 =  0.0020833333f;      //  1/480
        b3 = -2.1081349e-4f;      // -17/80640
        b4 =  2.1356855e-5f;      //  31/1451520
    }

    bool inc[NQ];
#pragma unroll
    for (int k = 0; k < NQ; k++)
        inc[k] = (k == 0) ? (q != 0) : ((q == 0) || (k <= q));

    float hx = 0.f, cx = 0.f;
    // 2-deep prefetch of ax
    float a0 = g_ax[lane];
    float a1 = g_ax[32 + lane];

#pragma unroll 2
    for (int t = 0; t < SEQ; t++) {
        const float a = a0;
        a0 = a1;
        const int tn = (t + 2 < SEQ) ? (t + 2) : (SEQ - 1);
        a1 = g_ax[tn * 32 + lane];

        // ---- stage A: broadcast hx, recurrent matvec ----
        const float h0 = __shfl_sync(FULL, hx, 0);
        const float h1 = __shfl_sync(FULL, hx, 1);
        const float h2 = __shfl_sync(FULL, hx, 2);
        const float h3 = __shfl_sync(FULL, hx, 3);
        const float h4 = __shfl_sync(FULL, hx, 4);
        const float h5 = __shfl_sync(FULL, hx, 5);
        const float h6 = __shfl_sync(FULL, hx, 6);
        const float h7 = __shfl_sync(FULL, hx, 7);

        float c0 = fmaf(w[1], h1, fmaf(w[0], h0, a));
        float c1 = fmaf(w[3], h3, w[2] * h2);
        float c2 = fmaf(w[5], h5, w[4] * h4);
        float c3 = fmaf(w[7], h7, w[6] * h6);
        const float ang = (c0 + c1) + (c2 + c3);

        float cc = __cosf(ang);
        cc = cc * cc;

        // ---- stage B: gather cos^2, masked product ----
        float m[NQ];
#pragma unroll
        for (int k = 0; k < NQ; k++) {
            const float v = __shfl_sync(FULL, cc, base + k);
            m[k] = inc[k] ? v : 1.0f;
        }
        const float p = ((m[0] * m[1]) * (m[2] * m[3])) *
                        ((m[4] * m[5]) * (m[6] * m[7]));

        // ---- activation: division-free odd polynomial ----
        const float u = p * p;
        const float B = fmaf(fmaf(fmaf(fmaf(b4, u, b3), u, b2), u, b1), u, b0);
        const float act = fmaf(p, B, C);

        // ---- stage C: gather f,i,g,o for my wire ----
        const float fg = __shfl_sync(FULL, act, q);
        const float ig = __shfl_sync(FULL, act, 8 + q);
        const float gg = __shfl_sync(FULL, act, 16 + q);
        const float og = __shfl_sync(FULL, act, 24 + q);

        cx = fmaf(fg, cx, ig * gg);

        // hx = og * tanh(cx) via Pade: (og*cx*numc) * rcp(denc)
        const float tc   = cx * cx;
        const float numc = fmaf(tc + 105.f, tc, 945.f);
        const float denc = fmaf(fmaf(15.f, tc, 420.f), tc, 945.f);
        const float ocn  = (og * cx) * numc;
        hx = ocn * __fdividef(1.0f, denc);

        if (lane < NQ)
            g_h[t * NQ + lane] = hx;
    }
}

// ---------------------------------------------------------------------------
// Kernel 3: logits = h @ Wt^T + bt, then log_softmax over 50 tags.
// One block (32 threads) per timestep; lane handles tags {lane, lane+32}.
// ---------------------------------------------------------------------------
__global__ void logits_kernel(const float* __restrict__ Wt, const float* __restrict__ bt,
                              float* __restrict__ out) {
    const unsigned FULL = 0xffffffffu;
    const int t = blockIdx.x;
    const int lane = threadIdx.x;

    float h[NQ];
#pragma unroll
    for (int k = 0; k < NQ; k++)
        h[k] = g_h[t * NQ + k];

    float l0 = bt[lane];
#pragma unroll
    for (int k = 0; k < NQ; k++)
        l0 = fmaf(Wt[lane * NQ + k], h[k], l0);

    const int tag1 = lane + 32;
    const bool v1 = (tag1 < TAGS);
    float l1 = -3.0e38f;
    if (v1) {
        l1 = bt[tag1];
#pragma unroll
        for (int k = 0; k < NQ; k++)
            l1 = fmaf(Wt[tag1 * NQ + k], h[k], l1);
    }

    float mx = fmaxf(l0, l1);
#pragma unroll
    for (int d = 16; d; d >>= 1)
        mx = fmaxf(mx, __shfl_xor_sync(FULL, mx, d));

    float se = expf(l0 - mx) + (v1 ? expf(l1 - mx) : 0.f);
#pragma unroll
    for (int d = 16; d; d >>= 1)
        se += __shfl_xor_sync(FULL, se, d);

    const float ls = mx + logf(se);
    out[t * TAGS + lane] = l0 - ls;
    if (v1)
        out[t * TAGS + tag1] = l1 - ls;
}

// ---------------------------------------------------------------------------
extern "C" void kernel_launch(void* const* d_in, const int* in_sizes, int n_in,
                              void* d_out, int out_size) {
    const int*   sent = (const int*)  d_in[0];
    const float* emb  = (const float*)d_in[1];
    const float* Wf   = (const float*)d_in[2];
    const float* bf   = (const float*)d_in[3];
    const float* Wi   = (const float*)d_in[4];
    const float* bi   = (const float*)d_in[5];
    const float* Wu   = (const float*)d_in[6];
    const float* bu   = (const float*)d_in[7];
    const float* Wo   = (const float*)d_in[8];
    const float* bo   = (const float*)d_in[9];
    const float* Wt   = (const float*)d_in[10];
    const float* bt   = (const float*)d_in[11];
    float* out = (float*)d_out;

    precompute_kernel<<<SEQ / TCHUNK, 256>>>(sent, emb, Wf, bf, Wi, bi, Wu, bu, Wo, bo);
    scan_kernel<<<1, 32>>>(Wf, Wi, Wu, Wo);
    logits_kernel<<<SEQ, 32>>>(Wt, bt, out);
}

// round 8
// speedup vs baseline: 25.6970x; 20.1152x over previous
#include <cuda_runtime.h>
#include <cuda_bf16.h>

#define SEQ   4096
#define EMBED 256
#define NQ    8
#define TAGS  50
#define DIN   264   // EMBED + NQ
#define TCHUNK 16   // timesteps per precompute block
#define CHUNK  16   // timesteps owned per scan block
#define WARM   96   // warmup steps (contraction >= 0.88^96 ~ 5e-6)

// Scratch (device globals — no dynamic allocation allowed)
__device__ float g_ax[SEQ * 32];   // [t][gate][q] pre-activations from x_t (+bias)
__device__ float g_h[SEQ * NQ];    // lstm hidden outputs

// ---------------------------------------------------------------------------
// Kernel 1: ax[t][g][q] = W_g[q, :256] @ emb[sentence[t]] + b_g[q]
// 256 blocks x 16 timesteps. Weights in registers (32/thread), embedding row
// double-buffered in padded (conflict-free) smem. 8 threads per (g,q) output.
// ---------------------------------------------------------------------------
__global__ void __launch_bounds__(256) precompute_kernel(
        const int* __restrict__ sent, const float* __restrict__ emb,
        const float* __restrict__ Wf, const float* __restrict__ bf,
        const float* __restrict__ Wi, const float* __restrict__ bi,
        const float* __restrict__ Wu, const float* __restrict__ bu,
        const float* __restrict__ Wo, const float* __restrict__ bo) {
    __shared__ float xe[2][264];               // 256 elems padded: idx + (idx>>5)

    const int tid  = threadIdx.x;
    const int t0   = blockIdx.x * TCHUNK;
    const int outi = tid >> 3;                 // 0..31 : gate*8 + q
    const int g    = outi >> 3;
    const int q    = outi & 7;
    const int sub  = tid & 7;

    const float* W = (g == 0) ? Wf : (g == 1) ? Wi : (g == 2) ? Wu : Wo;
    const float* b = (g == 0) ? bf : (g == 1) ? bi : (g == 2) ? bu : bo;

    // weights for my 32-element slice of the dot product -> registers
    float wreg[32];
    const float* row = W + q * DIN + sub * 32;
#pragma unroll
    for (int j = 0; j < 32; j++) wreg[j] = row[j];
    const float bias = b[q];

    // preload first embedding row
    {
        const int s = sent[t0];
        xe[0][tid + (tid >> 5)] = emb[(size_t)s * EMBED + tid];
    }
    __syncthreads();

    const int pbase = sub * 33;                // padded base for reads

    for (int i = 0; i < TCHUNK; i++) {
        const int buf = i & 1;
        const int t   = t0 + i;

        float nxt = 0.f;
        if (i + 1 < TCHUNK) {
            const int s2 = sent[t + 1];
            nxt = emb[(size_t)s2 * EMBED + tid];
        }

        float acc = 0.f;
#pragma unroll
        for (int j = 0; j < 32; j++)
            acc = fmaf(wreg[j], xe[buf][pbase + j], acc);

        acc += __shfl_xor_sync(0xffffffffu, acc, 4);
        acc += __shfl_xor_sync(0xffffffffu, acc, 2);
        acc += __shfl_xor_sync(0xffffffffu, acc, 1);

        if (sub == 0)
            g_ax[t * 32 + outi] = acc + bias;

        if (i + 1 < TCHUNK)
            xe[buf ^ 1][tid + (tid >> 5)] = nxt;
        __syncthreads();
    }
}

// ---------------------------------------------------------------------------
// Kernel 2: chunked LSTM scan. 256 blocks x 1 warp; block c owns timesteps
// [c*CHUNK, (c+1)*CHUNK) and warms up from max(0, c*CHUNK - WARM) starting at
// state (0,0). The recurrence contracts by <=~0.88/step (forget gate
// sigma(p), p in [0,1] => f in [0.5,0.731]), so WARM=96 warmup makes the
// truncated history contribution <= ~5e-6.
// Quantum layer collapses analytically:
//   z_j = prod_{k<=j} cos^2(a_k)  (j>=1);   z_0 = prod_{k=1..7} cos^2(a_k)
// Gate activations: act = C + p*B(p^2), division-free odd polynomial.
// Output tanh(cx) keeps Pade(9) rational (cx in [-2.1, 2.1]).
// ---------------------------------------------------------------------------
__global__ void __launch_bounds__(32, 1) scan_kernel(
        const float* __restrict__ Wf, const float* __restrict__ Wi,
        const float* __restrict__ Wu, const float* __restrict__ Wo) {
    const unsigned FULL = 0xffffffffu;
    const int lane = threadIdx.x;          // 0..31
    const int g = lane >> 3, q = lane & 7;
    const int base = g << 3;

    const int t0     = blockIdx.x * CHUNK;
    const int tstart = (t0 > WARM) ? (t0 - WARM) : 0;
    const int tend   = t0 + CHUNK;

    const float* W = (g == 0) ? Wf : (g == 1) ? Wi : (g == 2) ? Wu : Wo;
    float w[NQ];
#pragma unroll
    for (int k = 0; k < NQ; k++)
        w[k] = W[q * DIN + EMBED + k];     // recurrent slice W[:, 256:264]

    // per-lane activation polynomial: act = C + p*(b0 + b1 u + b2 u^2 + b3 u^3 + b4 u^4)
    float C, b0, b1, b2, b3, b4;
    if (g == 2) {  // tanh gate
        C  = 0.0f;
        b0 = 1.0f;
        b1 = -0.33325783f;
        b2 =  0.13215491f;
        b3 = -0.04825764f;
        b4 =  0.01095456f;
    } else {       // sigmoid gates
        C  = 0.5f;
        b0 =  0.25f;
        b1 = -0.020833333f;       // -1/48
        b2 =  0.0020833333f;      //  1/480
        b3 = -2.1081349e-4f;      // -17/80640
        b4 =  2.1356855e-5f;      //  31/1451520
    }

    bool inc[NQ];
#pragma unroll
    for (int k = 0; k < NQ; k++)
        inc[k] = (k == 0) ? (q != 0) : ((q == 0) || (k <= q));

    float hx = 0.f, cx = 0.f;
    // 2-deep prefetch of ax
    float a0 = g_ax[tstart * 32 + lane];
    float a1 = g_ax[(tstart + 1) * 32 + lane];

#pragma unroll 2
    for (int t = tstart; t < tend; t++) {
        const float a = a0;
        a0 = a1;
        const int tn = (t + 2 < SEQ) ? (t + 2) : (SEQ - 1);
        a1 = g_ax[tn * 32 + lane];

        // ---- stage A: broadcast hx, recurrent matvec ----
        const float h0 = __shfl_sync(FULL, hx, 0);
        const float h1 = __shfl_sync(FULL, hx, 1);
        const float h2 = __shfl_sync(FULL, hx, 2);
        const float h3 = __shfl_sync(FULL, hx, 3);
        const float h4 = __shfl_sync(FULL, hx, 4);
        const float h5 = __shfl_sync(FULL, hx, 5);
        const float h6 = __shfl_sync(FULL, hx, 6);
        const float h7 = __shfl_sync(FULL, hx, 7);

        float c0 = fmaf(w[1], h1, fmaf(w[0], h0, a));
        float c1 = fmaf(w[3], h3, w[2] * h2);
        float c2 = fmaf(w[5], h5, w[4] * h4);
        float c3 = fmaf(w[7], h7, w[6] * h6);
        const float ang = (c0 + c1) + (c2 + c3);

        float cc = __cosf(ang);
        cc = cc * cc;

        // ---- stage B: gather cos^2, masked product ----
        float m[NQ];
#pragma unroll
        for (int k = 0; k < NQ; k++) {
            const float v = __shfl_sync(FULL, cc, base + k);
            m[k] = inc[k] ? v : 1.0f;
        }
        const float p = ((m[0] * m[1]) * (m[2] * m[3])) *
                        ((m[4] * m[5]) * (m[6] * m[7]));

        // ---- activation: division-free odd polynomial ----
        const float u = p * p;
        const float B = fmaf(fmaf(fmaf(fmaf(b4, u, b3), u, b2), u, b1), u, b0);
        const float act = fmaf(p, B, C);

        // ---- stage C: gather f,i,g,o for my wire ----
        const float fg = __shfl_sync(FULL, act, q);
        const float ig = __shfl_sync(FULL, act, 8 + q);
        const float gg = __shfl_sync(FULL, act, 16 + q);
        const float og = __shfl_sync(FULL, act, 24 + q);

        cx = fmaf(fg, cx, ig * gg);

        // hx = og * tanh(cx) via Pade: (og*cx*numc) * rcp(denc)
        const float tc   = cx * cx;
        const float numc = fmaf(tc + 105.f, tc, 945.f);
        const float denc = fmaf(fmaf(15.f, tc, 420.f), tc, 945.f);
        const float ocn  = (og * cx) * numc;
        hx = ocn * __fdividef(1.0f, denc);

        if (t >= t0 && lane < NQ)
            g_h[t * NQ + lane] = hx;
    }
}

// ---------------------------------------------------------------------------
// Kernel 3: logits = h @ Wt^T + bt, then log_softmax over 50 tags.
// One block (32 threads) per timestep; lane handles tags {lane, lane+32}.
// ---------------------------------------------------------------------------
__global__ void logits_kernel(const float* __restrict__ Wt, const float* __restrict__ bt,
                              float* __restrict__ out) {
    const unsigned FULL = 0xffffffffu;
    const int t = blockIdx.x;
    const int lane = threadIdx.x;

    float h[NQ];
#pragma unroll
    for (int k = 0; k < NQ; k++)
        h[k] = g_h[t * NQ + k];

    float l0 = bt[lane];
#pragma unroll
    for (int k = 0; k < NQ; k++)
        l0 = fmaf(Wt[lane * NQ + k], h[k], l0);

    const int tag1 = lane + 32;
    const bool v1 = (tag1 < TAGS);
    float l1 = -3.0e38f;
    if (v1) {
        l1 = bt[tag1];
#pragma unroll
        for (int k = 0; k < NQ; k++)
            l1 = fmaf(Wt[tag1 * NQ + k], h[k], l1);
    }

    float mx = fmaxf(l0, l1);
#pragma unroll
    for (int d = 16; d; d >>= 1)
        mx = fmaxf(mx, __shfl_xor_sync(FULL, mx, d));

    float se = expf(l0 - mx) + (v1 ? expf(l1 - mx) : 0.f);
#pragma unroll
    for (int d = 16; d; d >>= 1)
        se += __shfl_xor_sync(FULL, se, d);

    const float ls = mx + logf(se);
    out[t * TAGS + lane] = l0 - ls;
    if (v1)
        out[t * TAGS + tag1] = l1 - ls;
}

// ---------------------------------------------------------------------------
extern "C" void kernel_launch(void* const* d_in, const int* in_sizes, int n_in,
                              void* d_out, int out_size) {
    const int*   sent = (const int*)  d_in[0];
    const float* emb  = (const float*)d_in[1];
    const float* Wf   = (const float*)d_in[2];
    const float* bf   = (const float*)d_in[3];
    const float* Wi   = (const float*)d_in[4];
    const float* bi   = (const float*)d_in[5];
    const float* Wu   = (const float*)d_in[6];
    const float* bu   = (const float*)d_in[7];
    const float* Wo   = (const float*)d_in[8];
    const float* bo   = (const float*)d_in[9];
    const float* Wt   = (const float*)d_in[10];
    const float* bt   = (const float*)d_in[11];
    float* out = (float*)d_out;

    precompute_kernel<<<SEQ / TCHUNK, 256>>>(sent, emb, Wf, bf, Wi, bi, Wu, bu, Wo, bo);
    scan_kernel<<<SEQ / CHUNK, 32>>>(Wf, Wi, Wu, Wo);
    logits_kernel<<<SEQ, 32>>>(Wt, bt, out);
}

// round 9
// speedup vs baseline: 30.4963x; 1.1868x over previous
#include <cuda_runtime.h>
#include <cuda_bf16.h>

#define SEQ   4096
#define EMBED 256
#define NQ    8
#define TAGS  50
#define DIN   264   // EMBED + NQ
#define TCHUNK 16   // timesteps per precompute block
#define CHUNK  8    // timesteps owned per scan block
#define WARM   64   // warmup steps (measured contraction < 0.82/step -> <3e-6)

// Scratch (device globals — no dynamic allocation allowed)
__device__ float g_ax[SEQ * 32];   // [t][gate][q] pre-activations from x_t (+bias)
__device__ float g_h[SEQ * NQ];    // lstm hidden outputs

// ---------------------------------------------------------------------------
// Kernel 1: ax[t][g][q] = W_g[q, :256] @ emb[sentence[t]] + b_g[q]
// 256 blocks x 16 timesteps. Weights in registers (32/thread), embedding row
// double-buffered in padded (conflict-free) smem. 8 threads per (g,q) output.
// Dot product uses 4 independent accumulators (chain 128cy -> ~36cy).
// ---------------------------------------------------------------------------
__global__ void __launch_bounds__(256) precompute_kernel(
        const int* __restrict__ sent, const float* __restrict__ emb,
        const float* __restrict__ Wf, const float* __restrict__ bf,
        const float* __restrict__ Wi, const float* __restrict__ bi,
        const float* __restrict__ Wu, const float* __restrict__ bu,
        const float* __restrict__ Wo, const float* __restrict__ bo) {
    __shared__ float xe[2][264];               // 256 elems padded: idx + (idx>>5)

    const int tid  = threadIdx.x;
    const int t0   = blockIdx.x * TCHUNK;
    const int outi = tid >> 3;                 // 0..31 : gate*8 + q
    const int g    = outi >> 3;
    const int q    = outi & 7;
    const int sub  = tid & 7;

    const float* W = (g == 0) ? Wf : (g == 1) ? Wi : (g == 2) ? Wu : Wo;
    const float* b = (g == 0) ? bf : (g == 1) ? bi : (g == 2) ? bu : bo;

    // weights for my 32-element slice of the dot product -> registers
    float wreg[32];
    const float* row = W + q * DIN + sub * 32;
#pragma unroll
    for (int j = 0; j < 32; j++) wreg[j] = row[j];
    const float bias = b[q];

    // preload first embedding row
    {
        const int s = sent[t0];
        xe[0][tid + (tid >> 5)] = emb[(size_t)s * EMBED + tid];
    }
    __syncthreads();

    const int pbase = sub * 33;                // padded base for reads

    for (int i = 0; i < TCHUNK; i++) {
        const int buf = i & 1;
        const int t   = t0 + i;

        float nxt = 0.f;
        if (i + 1 < TCHUNK) {
            const int s2 = sent[t + 1];
            nxt = emb[(size_t)s2 * EMBED + tid];
        }

        // 4 independent accumulator chains
        float ac0 = 0.f, ac1 = 0.f, ac2 = 0.f, ac3 = 0.f;
#pragma unroll
        for (int j = 0; j < 32; j += 4) {
            ac0 = fmaf(wreg[j + 0], xe[buf][pbase + j + 0], ac0);
            ac1 = fmaf(wreg[j + 1], xe[buf][pbase + j + 1], ac1);
            ac2 = fmaf(wreg[j + 2], xe[buf][pbase + j + 2], ac2);
            ac3 = fmaf(wreg[j + 3], xe[buf][pbase + j + 3], ac3);
        }
        float acc = (ac0 + ac1) + (ac2 + ac3);

        acc += __shfl_xor_sync(0xffffffffu, acc, 4);
        acc += __shfl_xor_sync(0xffffffffu, acc, 2);
        acc += __shfl_xor_sync(0xffffffffu, acc, 1);

        if (sub == 0)
            g_ax[t * 32 + outi] = acc + bias;

        if (i + 1 < TCHUNK)
            xe[buf ^ 1][tid + (tid >> 5)] = nxt;
        __syncthreads();
    }
}

// ---------------------------------------------------------------------------
// Kernel 2: chunked LSTM scan. 512 blocks x 1 warp; block c owns timesteps
// [c*CHUNK, (c+1)*CHUNK) and warms up from max(0, c*CHUNK - WARM) starting at
// state (0,0). Measured (R8): WARM=96 truncation was invisible vs the serial
// run => contraction < 0.82/step => WARM=64 gives < ~3e-6 truncation.
// Quantum layer collapses analytically:
//   z_j = prod_{k<=j} cos^2(a_k)  (j>=1);   z_0 = prod_{k=1..7} cos^2(a_k)
// Gate activations: act = C + p*B(p^2), division-free odd polynomial.
// Output tanh(cx) keeps Pade(9) rational (cx in [-2.1, 2.1]).
// ---------------------------------------------------------------------------
__global__ void __launch_bounds__(32, 1) scan_kernel(
        const float* __restrict__ Wf, const float* __restrict__ Wi,
        const float* __restrict__ Wu, const float* __restrict__ Wo) {
    const unsigned FULL = 0xffffffffu;
    const int lane = threadIdx.x;          // 0..31
    const int g = lane >> 3, q = lane & 7;
    const int base = g << 3;

    const int t0     = blockIdx.x * CHUNK;
    const int tstart = (t0 > WARM) ? (t0 - WARM) : 0;
    const int tend   = t0 + CHUNK;

    const float* W = (g == 0) ? Wf : (g == 1) ? Wi : (g == 2) ? Wu : Wo;
    float w[NQ];
#pragma unroll
    for (int k = 0; k < NQ; k++)
        w[k] = W[q * DIN + EMBED + k];     // recurrent slice W[:, 256:264]

    // per-lane activation polynomial: act = C + p*(b0 + b1 u + b2 u^2 + b3 u^3 + b4 u^4)
    float C, b0, b1, b2, b3, b4;
    if (g == 2) {  // tanh gate
        C  = 0.0f;
        b0 = 1.0f;
        b1 = -0.33325783f;
        b2 =  0.13215491f;
        b3 = -0.04825764f;
        b4 =  0.01095456f;
    } else {       // sigmoid gates
        C  = 0.5f;
        b0 =  0.25f;
        b1 = -0.020833333f;       // -1/48
        b2 =  0.0020833333f;      //  1/480
        b3 = -2.1081349e-4f;      // -17/80640
        b4 =  2.1356855e-5f;      //  31/1451520
    }

    bool inc[NQ];
#pragma unroll
    for (int k = 0; k < NQ; k++)
        inc[k] = (k == 0) ? (q != 0) : ((q == 0) || (k <= q));

    float hx = 0.f, cx = 0.f;
    // 2-deep prefetch of ax
    float a0 = g_ax[tstart * 32 + lane];
    float a1 = g_ax[(tstart + 1) * 32 + lane];

#pragma unroll 2
    for (int t = tstart; t < tend; t++) {
        const float a = a0;
        a0 = a1;
        const int tn = (t + 2 < SEQ) ? (t + 2) : (SEQ - 1);
        a1 = g_ax[tn * 32 + lane];

        // ---- stage A: broadcast hx, recurrent matvec ----
        const float h0 = __shfl_sync(FULL, hx, 0);
        const float h1 = __shfl_sync(FULL, hx, 1);
        const float h2 = __shfl_sync(FULL, hx, 2);
        const float h3 = __shfl_sync(FULL, hx, 3);
        const float h4 = __shfl_sync(FULL, hx, 4);
        const float h5 = __shfl_sync(FULL, hx, 5);
        const float h6 = __shfl_sync(FULL, hx, 6);
        const float h7 = __shfl_sync(FULL, hx, 7);

        float c0 = fmaf(w[1], h1, fmaf(w[0], h0, a));
        float c1 = fmaf(w[3], h3, w[2] * h2);
        float c2 = fmaf(w[5], h5, w[4] * h4);
        float c3 = fmaf(w[7], h7, w[6] * h6);
        const float ang = (c0 + c1) + (c2 + c3);

        float cc = __cosf(ang);
        cc = cc * cc;

        // ---- stage B: gather cos^2, masked product ----
        float m[NQ];
#pragma unroll
        for (int k = 0; k < NQ; k++) {
            const float v = __shfl_sync(FULL, cc, base + k);
            m[k] = inc[k] ? v : 1.0f;
        }
        const float p = ((m[0] * m[1]) * (m[2] * m[3])) *
                        ((m[4] * m[5]) * (m[6] * m[7]));

        // ---- activation: division-free odd polynomial ----
        const float u = p * p;
        const float B = fmaf(fmaf(fmaf(fmaf(b4, u, b3), u, b2), u, b1), u, b0);
        const float act = fmaf(p, B, C);

        // ---- stage C: gather f,i,g,o for my wire ----
        const float fg = __shfl_sync(FULL, act, q);
        const float ig = __shfl_sync(FULL, act, 8 + q);
        const float gg = __shfl_sync(FULL, act, 16 + q);
        const float og = __shfl_sync(FULL, act, 24 + q);

        cx = fmaf(fg, cx, ig * gg);

        // hx = og * tanh(cx) via Pade: (og*cx*numc) * rcp(denc)
        const float tc   = cx * cx;
        const float numc = fmaf(tc + 105.f, tc, 945.f);
        const float denc = fmaf(fmaf(15.f, tc, 420.f), tc, 945.f);
        const float ocn  = (og * cx) * numc;
        hx = ocn * __fdividef(1.0f, denc);

        if (t >= t0 && lane < NQ)
            g_h[t * NQ + lane] = hx;
    }
}

// ---------------------------------------------------------------------------
// Kernel 3: logits = h @ Wt^T + bt, then log_softmax over 50 tags.
// One block (32 threads) per timestep; lane handles tags {lane, lane+32}.
// ---------------------------------------------------------------------------
__global__ void logits_kernel(const float* __restrict__ Wt, const float* __restrict__ bt,
                              float* __restrict__ out) {
    const unsigned FULL = 0xffffffffu;
    const int t = blockIdx.x;
    const int lane = threadIdx.x;

    float h[NQ];
#pragma unroll
    for (int k = 0; k < NQ; k++)
        h[k] = g_h[t * NQ + k];

    float l0 = bt[lane];
#pragma unroll
    for (int k = 0; k < NQ; k++)
        l0 = fmaf(Wt[lane * NQ + k], h[k], l0);

    const int tag1 = lane + 32;
    const bool v1 = (tag1 < TAGS);
    float l1 = -3.0e38f;
    if (v1) {
        l1 = bt[tag1];
#pragma unroll
        for (int k = 0; k < NQ; k++)
            l1 = fmaf(Wt[tag1 * NQ + k], h[k], l1);
    }

    float mx = fmaxf(l0, l1);
#pragma unroll
    for (int d = 16; d; d >>= 1)
        mx = fmaxf(mx, __shfl_xor_sync(FULL, mx, d));

    float se = expf(l0 - mx) + (v1 ? expf(l1 - mx) : 0.f);
#pragma unroll
    for (int d = 16; d; d >>= 1)
        se += __shfl_xor_sync(FULL, se, d);

    const float ls = mx + logf(se);
    out[t * TAGS + lane] = l0 - ls;
    if (v1)
        out[t * TAGS + tag1] = l1 - ls;
}

// ---------------------------------------------------------------------------
extern "C" void kernel_launch(void* const* d_in, const int* in_sizes, int n_in,
                              void* d_out, int out_size) {
    const int*   sent = (const int*)  d_in[0];
    const float* emb  = (const float*)d_in[1];
    const float* Wf   = (const float*)d_in[2];
    const float* bf   = (const float*)d_in[3];
    const float* Wi   = (const float*)d_in[4];
    const float* bi   = (const float*)d_in[5];
    const float* Wu   = (const float*)d_in[6];
    const float* bu   = (const float*)d_in[7];
    const float* Wo   = (const float*)d_in[8];
    const float* bo   = (const float*)d_in[9];
    const float* Wt   = (const float*)d_in[10];
    const float* bt   = (const float*)d_in[11];
    float* out = (float*)d_out;

    precompute_kernel<<<SEQ / TCHUNK, 256>>>(sent, emb, Wf, bf, Wi, bi, Wu, bu, Wo, bo);
    scan_kernel<<<SEQ / CHUNK, 32>>>(Wf, Wi, Wu, Wo);
    logits_kernel<<<SEQ, 32>>>(Wt, bt, out);
}

// round 11
// speedup vs baseline: 35.5703x; 1.1664x over previous
#include <cuda_runtime.h>
#include <cuda_bf16.h>

#define SEQ   4096
#define EMBED 256
#define NQ    8
#define TAGS  50
#define DIN   264   // EMBED + NQ
#define TCHUNK 16   // timesteps per precompute block
#define CHUNK  8    // timesteps owned per scan block
#define WARM   40   // warmup steps (measured worst contraction ~0.67/step -> ~1e-7)

// Scratch (device globals — no dynamic allocation allowed)
__device__ float g_ax[SEQ * 32];   // [t][gate][q] pre-activations from x_t (+bias)
__device__ float g_h[SEQ * NQ];    // lstm hidden outputs

// ---------------------------------------------------------------------------
// Kernel 1: ax[t][g][q] = W_g[q, :256] @ emb[sentence[t]] + b_f[q]
// 256 blocks x 16 timesteps. Weights in registers (32/thread).
// emb row LDG issued ONE FULL ITERATION before its smem store (2-body latency
// window, covers DRAM); sentence indices preloaded + shuffle-broadcast so the
// dependent sent->emb chain is gone. Double-buffered padded smem.
// ---------------------------------------------------------------------------
__global__ void __launch_bounds__(256) precompute_kernel(
        const int* __restrict__ sent, const float* __restrict__ emb,
        const float* __restrict__ Wf, const float* __restrict__ bf,
        const float* __restrict__ Wi, const float* __restrict__ bi,
        const float* __restrict__ Wu, const float* __restrict__ bu,
        const float* __restrict__ Wo, const float* __restrict__ bo) {
    __shared__ float xe[2][264];               // 256 elems padded: idx + (idx>>5)

    const unsigned FULL = 0xffffffffu;
    const int tid  = threadIdx.x;
    const int lane = tid & 31;
    const int t0   = blockIdx.x * TCHUNK;
    const int outi = tid >> 3;                 // 0..31 : gate*8 + q
    const int g    = outi >> 3;
    const int q    = outi & 7;
    const int sub  = tid & 7;

    const float* W = (g == 0) ? Wf : (g == 1) ? Wi : (g == 2) ? Wu : Wo;
    const float* b = (g == 0) ? bf : (g == 1) ? bi : (g == 2) ? bu : bo;

    // each warp holds the 16 sentence indices in lanes 0..15
    const int sidx = sent[t0 + (lane & 15)];

    // weights for my 32-element slice of the dot product -> registers
    float wreg[32];
    const float* row = W + q * DIN + sub * 32;
#pragma unroll
    for (int j = 0; j < 32; j++) wreg[j] = row[j];
    const float bias = b[q];

    // preload row 0 into buf0; issue row 1 load (held in r1 across iter 0)
    {
        const int s0 = __shfl_sync(FULL, sidx, 0);
        xe[0][tid + (tid >> 5)] = emb[(size_t)s0 * EMBED + tid];
    }
    const int s1 = __shfl_sync(FULL, sidx, 1);
    float r1 = emb[(size_t)s1 * EMBED + tid];   // in flight through iter 0
    __syncthreads();

    const int pbase = sub * 33;                // padded base for reads

    for (int i = 0; i < TCHUNK; i++) {
        const int buf = i & 1;
        const int t   = t0 + i;

        // issue load for row i+2 NOW; it is stored at the END of iter i+1
        float r2 = 0.f;
        if (i + 2 < TCHUNK) {
            const int s2 = __shfl_sync(FULL, sidx, (i + 2) & 15);
            r2 = emb[(size_t)s2 * EMBED + tid];
        }

        // 4 independent accumulator chains
        float ac0 = 0.f, ac1 = 0.f, ac2 = 0.f, ac3 = 0.f;
#pragma unroll
        for (int j = 0; j < 32; j += 4) {
            ac0 = fmaf(wreg[j + 0], xe[buf][pbase + j + 0], ac0);
            ac1 = fmaf(wreg[j + 1], xe[buf][pbase + j + 1], ac1);
            ac2 = fmaf(wreg[j + 2], xe[buf][pbase + j + 2], ac2);
            ac3 = fmaf(wreg[j + 3], xe[buf][pbase + j + 3], ac3);
        }
        float acc = (ac0 + ac1) + (ac2 + ac3);

        acc += __shfl_xor_sync(FULL, acc, 4);
        acc += __shfl_xor_sync(FULL, acc, 2);
        acc += __shfl_xor_sync(FULL, acc, 1);

        if (sub == 0)
            g_ax[t * 32 + outi] = acc + bias;

        // store row i+1 (loaded one full iteration ago) into the other buffer
        if (i + 1 < TCHUNK)
            xe[buf ^ 1][tid + (tid >> 5)] = r1;
        __syncthreads();

        r1 = r2;
    }
}

// ---------------------------------------------------------------------------
// Kernel 2: chunked LSTM scan. 512 blocks x 1 warp; block c owns timesteps
// [c*CHUNK, (c+1)*CHUNK) and warms up from max(0, c*CHUNK - WARM) starting at
// state (0,0). Measured: WARM=64 truncation perturbs outputs at ~6e-12 =>
// worst-case contraction ~0.67/step => WARM=40 truncation ~1e-7.
// Quantum layer collapses analytically:
//   z_j = prod_{k<=j} cos^2(a_k)  (j>=1);   z_0 = prod_{k=1..7} cos^2(a_k)
// Gate activations: act = C + p*B(p^2), division-free odd polynomial.
// Output tanh(cx) keeps Pade(9) rational (cx in [-2.1, 2.1]).
// ---------------------------------------------------------------------------
__global__ void __launch_bounds__(32, 1) scan_kernel(
        const float* __restrict__ Wf, const float* __restrict__ Wi,
        const float* __restrict__ Wu, const float* __restrict__ Wo) {
    const unsigned FULL = 0xffffffffu;
    const int lane = threadIdx.x;          // 0..31
    const int g = lane >> 3, q = lane & 7;
    const int base = g << 3;

    const int t0     = blockIdx.x * CHUNK;
    const int tstart = (t0 > WARM) ? (t0 - WARM) : 0;
    const int tend   = t0 + CHUNK;

    const float* W = (g == 0) ? Wf : (g == 1) ? Wi : (g == 2) ? Wu : Wo;
    float w[NQ];
#pragma unroll
    for (int k = 0; k < NQ; k++)
        w[k] = W[q * DIN + EMBED + k];     // recurrent slice W[:, 256:264]

    // per-lane activation polynomial: act = C + p*(b0 + b1 u + b2 u^2 + b3 u^3 + b4 u^4)
    float C, b0, b1, b2, b3, b4;
    if (g == 2) {  // tanh gate
        C  = 0.0f;
        b0 = 1.0f;
        b1 = -0.33325783f;
        b2 =  0.13215491f;
        b3 = -0.04825764f;
        b4 =  0.01095456f;
    } else {       // sigmoid gates
        C  = 0.5f;
        b0 =  0.25f;
        b1 = -0.020833333f;       // -1/48
        b2 =  0.0020833333f;      //  1/480
        b3 = -2.1081349e-4f;      // -17/80640
        b4 =  2.1356855e-5f;      //  31/1451520
    }

    bool inc[NQ];
#pragma unroll
    for (int k = 0; k < NQ; k++)
        inc[k] = (k == 0) ? (q != 0) : ((q == 0) || (k <= q));

    float hx = 0.f, cx = 0.f;
    // 2-deep prefetch of ax
    float a0 = g_ax[tstart * 32 + lane];
    float a1 = g_ax[(tstart + 1) * 32 + lane];

#pragma unroll 2
    for (int t = tstart; t < tend; t++) {
        const float a = a0;
        a0 = a1;
        const int tn = (t + 2 < SEQ) ? (t + 2) : (SEQ - 1);
        a1 = g_ax[tn * 32 + lane];

        // ---- stage A: broadcast hx, recurrent matvec ----
        const float h0 = __shfl_sync(FULL, hx, 0);
        const float h1 = __shfl_sync(FULL, hx, 1);
        const float h2 = __shfl_sync(FULL, hx, 2);
        const float h3 = __shfl_sync(FULL, hx, 3);
        const float h4 = __shfl_sync(FULL, hx, 4);
        const float h5 = __shfl_sync(FULL, hx, 5);
        const float h6 = __shfl_sync(FULL, hx, 6);
        const float h7 = __shfl_sync(FULL, hx, 7);

        float c0 = fmaf(w[1], h1, fmaf(w[0], h0, a));
        float c1 = fmaf(w[3], h3, w[2] * h2);
        float c2 = fmaf(w[5], h5, w[4] * h4);
        float c3 = fmaf(w[7], h7, w[6] * h6);
        const float ang = (c0 + c1) + (c2 + c3);

        float cc = __cosf(ang);
        cc = cc * cc;

        // ---- stage B: gather cos^2, masked product ----
        float m[NQ];
#pragma unroll
        for (int k = 0; k < NQ; k++) {
            const float v = __shfl_sync(FULL, cc, base + k);
            m[k] = inc[k] ? v : 1.0f;
        }
        const float p = ((m[0] * m[1]) * (m[2] * m[3])) *
                        ((m[4] * m[5]) * (m[6] * m[7]));

        // ---- activation: division-free odd polynomial ----
        const float u = p * p;
        const float B = fmaf(fmaf(fmaf(fmaf(b4, u, b3), u, b2), u, b1), u, b0);
        const float act = fmaf(p, B, C);

        // ---- stage C: gather f,i,g,o for my wire ----
        const float fg = __shfl_sync(FULL, act, q);
        const float ig = __shfl_sync(FULL, act, 8 + q);
        const float gg = __shfl_sync(FULL, act, 16 + q);
        const float og = __shfl_sync(FULL, act, 24 + q);

        cx = fmaf(fg, cx, ig * gg);

        // hx = og * tanh(cx) via Pade: (og*cx*numc) * rcp(denc)
        const float tc   = cx * cx;
        const float numc = fmaf(tc + 105.f, tc, 945.f);
        const float denc = fmaf(fmaf(15.f, tc, 420.f), tc, 945.f);
        const float ocn  = (og * cx) * numc;
        hx = ocn * __fdividef(1.0f, denc);

        if (t >= t0 && lane < NQ)
            g_h[t * NQ + lane] = hx;
    }
}

// ---------------------------------------------------------------------------
// Kernel 3: logits = h @ Wt^T + bt, then log_softmax over 50 tags.
// One block (32 threads) per timestep; lane handles tags {lane, lane+32}.
// ---------------------------------------------------------------------------
__global__ void logits_kernel(const float* __restrict__ Wt, const float* __restrict__ bt,
                              float* __restrict__ out) {
    const unsigned FULL = 0xffffffffu;
    const int t = blockIdx.x;
    const int lane = threadIdx.x;

    float h[NQ];
#pragma unroll
    for (int k = 0; k < NQ; k++)
        h[k] = g_h[t * NQ + k];

    float l0 = bt[lane];
#pragma unroll
    for (int k = 0; k < NQ; k++)
        l0 = fmaf(Wt[lane * NQ + k], h[k], l0);

    const int tag1 = lane + 32;
    const bool v1 = (tag1 < TAGS);
    float l1 = -3.0e38f;
    if (v1) {
        l1 = bt[tag1];
#pragma unroll
        for (int k = 0; k < NQ; k++)
            l1 = fmaf(Wt[tag1 * NQ + k], h[k], l1);
    }

    float mx = fmaxf(l0, l1);
#pragma unroll
    for (int d = 16; d; d >>= 1)
        mx = fmaxf(mx, __shfl_xor_sync(FULL, mx, d));

    float se = expf(l0 - mx) + (v1 ? expf(l1 - mx) : 0.f);
#pragma unroll
    for (int d = 16; d; d >>= 1)
        se += __shfl_xor_sync(FULL, se, d);

    const float ls = mx + logf(se);
    out[t * TAGS + lane] = l0 - ls;
    if (v1)
        out[t * TAGS + tag1] = l1 - ls;
}

// ---------------------------------------------------------------------------
extern "C" void kernel_launch(void* const* d_in, const int* in_sizes, int n_in,
                              void* d_out, int out_size) {
    const int*   sent = (const int*)  d_in[0];
    const float* emb  = (const float*)d_in[1];
    const float* Wf   = (const float*)d_in[2];
    const float* bf   = (const float*)d_in[3];
    const float* Wi   = (const float*)d_in[4];
    const float* bi   = (const float*)d_in[5];
    const float* Wu   = (const float*)d_in[6];
    const float* bu   = (const float*)d_in[7];
    const float* Wo   = (const float*)d_in[8];
    const float* bo   = (const float*)d_in[9];
    const float* Wt   = (const float*)d_in[10];
    const float* bt   = (const float*)d_in[11];
    float* out = (float*)d_out;

    precompute_kernel<<<SEQ / TCHUNK, 256>>>(sent, emb, Wf, bf, Wi, bi, Wu, bu, Wo, bo);
    scan_kernel<<<SEQ / CHUNK, 32>>>(Wf, Wi, Wu, Wo);
    logits_kernel<<<SEQ, 32>>>(Wt, bt, out);
}

// round 12
// speedup vs baseline: 37.2977x; 1.0486x over previous
#include <cuda_runtime.h>
#include <cuda_bf16.h>

#define SEQ   4096
#define EMBED 256
#define NQ    8
#define TAGS  50
#define DIN   264   // EMBED + NQ
#define CHUNK  8    // timesteps owned per scan block
#define WARM   32   // warmup steps (hard bound 0.731^32 ~ 4e-5; measured ~1e-8)

// Scratch (device globals — no dynamic allocation allowed)
__device__ float4 g_Wt4[64 * 32];  // [j4][outi] transposed input weights, float4 over j
__device__ float  g_bias[32];      // [outi] gate biases
__device__ float  g_ax[SEQ * 32];  // [t][gate][q] pre-activations from x_t (+bias)
__device__ float  g_h[SEQ * NQ];   // lstm hidden outputs

// ---------------------------------------------------------------------------
// Kernel 0: transpose input weights into [j4][outi] float4 layout + bias vec.
// Tiny one-shot: 2048 float4 elements.
// ---------------------------------------------------------------------------
__global__ void __launch_bounds__(256) transpose_kernel(
        const float* __restrict__ Wf, const float* __restrict__ bf,
        const float* __restrict__ Wi, const float* __restrict__ bi,
        const float* __restrict__ Wu, const float* __restrict__ bu,
        const float* __restrict__ Wo, const float* __restrict__ bo) {
    const int tid = threadIdx.x;
#pragma unroll
    for (int r = 0; r < 8; r++) {
        const int idx  = r * 256 + tid;        // 0..2047 = j4*32 + outi
        const int j4   = idx >> 5;
        const int outi = idx & 31;
        const int g    = outi >> 3;
        const int q    = outi & 7;
        const float* W = (g == 0) ? Wf : (g == 1) ? Wi : (g == 2) ? Wu : Wo;
        const float* row = W + q * DIN + j4 * 4;
        g_Wt4[idx] = make_float4(row[0], row[1], row[2], row[3]);
    }
    if (tid < 32) {
        const int g = tid >> 3, q = tid & 7;
        const float* b = (g == 0) ? bf : (g == 1) ? bi : (g == 2) ? bu : bo;
        g_bias[tid] = b[q];
    }
}

// ---------------------------------------------------------------------------
// Kernel 1: ax[t][outi] = W[outi,:256] @ emb[sentence[t]] + bias[outi]
// Warp-per-timestep, lane-per-output. No smem, no syncs, no reductions.
// Wt4 loads are lane-coalesced (512B/warp); emb4 loads are warp-broadcast
// (same address all lanes). 512 blocks x 8 warps.
// ---------------------------------------------------------------------------
__global__ void __launch_bounds__(256) ax_kernel(
        const int* __restrict__ sent, const float* __restrict__ emb) {
    const int tid  = threadIdx.x;
    const int warp = tid >> 5;
    const int lane = tid & 31;
    const int t    = blockIdx.x * 8 + warp;

    const int s = sent[t];                       // warp-uniform load
    const float4* __restrict__ e4 = (const float4*)emb + (size_t)s * 64;

    float ac0 = 0.f, ac1 = 0.f, ac2 = 0.f, ac3 = 0.f;
#pragma unroll 16
    for (int j4 = 0; j4 < 64; j4++) {
        const float4 wv = g_Wt4[j4 * 32 + lane];
        const float4 xv = e4[j4];
        ac0 = fmaf(wv.x, xv.x, ac0);
        ac1 = fmaf(wv.y, xv.y, ac1);
        ac2 = fmaf(wv.z, xv.z, ac2);
        ac3 = fmaf(wv.w, xv.w, ac3);
    }
    g_ax[t * 32 + lane] = ((ac0 + ac1) + (ac2 + ac3)) + g_bias[lane];
}

// ---------------------------------------------------------------------------
// Kernel 2: chunked LSTM scan. 512 blocks x 1 warp; block c owns timesteps
// [c*CHUNK, (c+1)*CHUNK) and warms up from max(0, c*CHUNK - WARM) starting at
// state (0,0). Measured: WARM=40 truncation perturbed rel_err at ~5e-11 =>
// contraction ~0.6/step; WARM=32 hard worst-case bound 0.731^32 ~ 4e-5 << 1e-3.
// Quantum layer collapses analytically:
//   z_j = prod_{k<=j} cos^2(a_k)  (j>=1);   z_0 = prod_{k=1..7} cos^2(a_k)
// Gate activations: act = C + p*B(p^2), division-free odd polynomial.
// Output tanh(cx) keeps Pade(9) rational (cx in [-2.1, 2.1]).
// ---------------------------------------------------------------------------
__global__ void __launch_bounds__(32, 1) scan_kernel(
        const float* __restrict__ Wf, const float* __restrict__ Wi,
        const float* __restrict__ Wu, const float* __restrict__ Wo) {
    const unsigned FULL = 0xffffffffu;
    const int lane = threadIdx.x;          // 0..31
    const int g = lane >> 3, q = lane & 7;
    const int base = g << 3;

    const int t0     = blockIdx.x * CHUNK;
    const int tstart = (t0 > WARM) ? (t0 - WARM) : 0;
    const int tend   = t0 + CHUNK;

    const float* W = (g == 0) ? Wf : (g == 1) ? Wi : (g == 2) ? Wu : Wo;
    float w[NQ];
#pragma unroll
    for (int k = 0; k < NQ; k++)
        w[k] = W[q * DIN + EMBED + k];     // recurrent slice W[:, 256:264]

    // per-lane activation polynomial: act = C + p*(b0 + b1 u + b2 u^2 + b3 u^3 + b4 u^4)
    float C, b0, b1, b2, b3, b4;
    if (g == 2) {  // tanh gate
        C  = 0.0f;
        b0 = 1.0f;
        b1 = -0.33325783f;
        b2 =  0.13215491f;
        b3 = -0.04825764f;
        b4 =  0.01095456f;
    } else {       // sigmoid gates
        C  = 0.5f;
        b0 =  0.25f;
        b1 = -0.020833333f;       // -1/48
        b2 =  0.0020833333f;      //  1/480
        b3 = -2.1081349e-4f;      // -17/80640
        b4 =  2.1356855e-5f;      //  31/1451520
    }

    bool inc[NQ];
#pragma unroll
    for (int k = 0; k < NQ; k++)
        inc[k] = (k == 0) ? (q != 0) : ((q == 0) || (k <= q));

    float hx = 0.f, cx = 0.f;
    // 2-deep prefetch of ax
    float a0 = g_ax[tstart * 32 + lane];
    float a1 = g_ax[(tstart + 1) * 32 + lane];

#pragma unroll 2
    for (int t = tstart; t < tend; t++) {
        const float a = a0;
        a0 = a1;
        const int tn = (t + 2 < SEQ) ? (t + 2) : (SEQ - 1);
        a1 = g_ax[tn * 32 + lane];

        // ---- stage A: broadcast hx, recurrent matvec ----
        const float h0 = __shfl_sync(FULL, hx, 0);
        const float h1 = __shfl_sync(FULL, hx, 1);
        const float h2 = __shfl_sync(FULL, hx, 2);
        const float h3 = __shfl_sync(FULL, hx, 3);
        const float h4 = __shfl_sync(FULL, hx, 4);
        const float h5 = __shfl_sync(FULL, hx, 5);
        const float h6 = __shfl_sync(FULL, hx, 6);
        const float h7 = __shfl_sync(FULL, hx, 7);

        float c0 = fmaf(w[1], h1, fmaf(w[0], h0, a));
        float c1 = fmaf(w[3], h3, w[2] * h2);
        float c2 = fmaf(w[5], h5, w[4] * h4);
        float c3 = fmaf(w[7], h7, w[6] * h6);
        const float ang = (c0 + c1) + (c2 + c3);

        float cc = __cosf(ang);
        cc = cc * cc;

        // ---- stage B: gather cos^2, masked product ----
        float m[NQ];
#pragma unroll
        for (int k = 0; k < NQ; k++) {
            const float v = __shfl_sync(FULL, cc, base + k);
            m[k] = inc[k] ? v : 1.0f;
        }
        const float p = ((m[0] * m[1]) * (m[2] * m[3])) *
                        ((m[4] * m[5]) * (m[6] * m[7]));

        // ---- activation: division-free odd polynomial ----
        const float u = p * p;
        const float B = fmaf(fmaf(fmaf(fmaf(b4, u, b3), u, b2), u, b1), u, b0);
        const float act = fmaf(p, B, C);

        // ---- stage C: gather f,i,g,o for my wire ----
        const float fg = __shfl_sync(FULL, act, q);
        const float ig = __shfl_sync(FULL, act, 8 + q);
        const float gg = __shfl_sync(FULL, act, 16 + q);
        const float og = __shfl_sync(FULL, act, 24 + q);

        cx = fmaf(fg, cx, ig * gg);

        // hx = og * tanh(cx) via Pade: (og*cx*numc) * rcp(denc)
        const float tc   = cx * cx;
        const float numc = fmaf(tc + 105.f, tc, 945.f);
        const float denc = fmaf(fmaf(15.f, tc, 420.f), tc, 945.f);
        const float ocn  = (og * cx) * numc;
        hx = ocn * __fdividef(1.0f, denc);

        if (t >= t0 && lane < NQ)
            g_h[t * NQ + lane] = hx;
    }
}

// ---------------------------------------------------------------------------
// Kernel 3: logits = h @ Wt^T + bt, then log_softmax over 50 tags.
// One block (32 threads) per timestep; lane handles tags {lane, lane+32}.
// ---------------------------------------------------------------------------
__global__ void logits_kernel(const float* __restrict__ Wt, const float* __restrict__ bt,
                              float* __restrict__ out) {
    const unsigned FULL = 0xffffffffu;
    const int t = blockIdx.x;
    const int lane = threadIdx.x;

    float h[NQ];
#pragma unroll
    for (int k = 0; k < NQ; k++)
        h[k] = g_h[t * NQ + k];

    float l0 = bt[lane];
#pragma unroll
    for (int k = 0; k < NQ; k++)
        l0 = fmaf(Wt[lane * NQ + k], h[k], l0);

    const int tag1 = lane + 32;
    const bool v1 = (tag1 < TAGS);
    float l1 = -3.0e38f;
    if (v1) {
        l1 = bt[tag1];
#pragma unroll
        for (int k = 0; k < NQ; k++)
            l1 = fmaf(Wt[tag1 * NQ + k], h[k], l1);
    }

    float mx = fmaxf(l0, l1);
#pragma unroll
    for (int d = 16; d; d >>= 1)
        mx = fmaxf(mx, __shfl_xor_sync(FULL, mx, d));

    float se = expf(l0 - mx) + (v1 ? expf(l1 - mx) : 0.f);
#pragma unroll
    for (int d = 16; d; d >>= 1)
        se += __shfl_xor_sync(FULL, se, d);

    const float ls = mx + logf(se);
    out[t * TAGS + lane] = l0 - ls;
    if (v1)
        out[t * TAGS + tag1] = l1 - ls;
}

// ---------------------------------------------------------------------------
extern "C" void kernel_launch(void* const* d_in, const int* in_sizes, int n_in,
                              void* d_out, int out_size) {
    const int*   sent = (const int*)  d_in[0];
    const float* emb  = (const float*)d_in[1];
    const float* Wf   = (const float*)d_in[2];
    const float* bf   = (const float*)d_in[3];
    const float* Wi   = (const float*)d_in[4];
    const float* bi   = (const float*)d_in[5];
    const float* Wu   = (const float*)d_in[6];
    const float* bu   = (const float*)d_in[7];
    const float* Wo   = (const float*)d_in[8];
    const float* bo   = (const float*)d_in[9];
    const float* Wt   = (const float*)d_in[10];
    const float* bt   = (const float*)d_in[11];
    float* out = (float*)d_out;

    transpose_kernel<<<1, 256>>>(Wf, bf, Wi, bi, Wu, bu, Wo, bo);
    ax_kernel<<<SEQ / 8, 256>>>(sent, emb);
    scan_kernel<<<SEQ / CHUNK, 32>>>(Wf, Wi, Wu, Wo);
    logits_kernel<<<SEQ, 32>>>(Wt, bt, out);
}

// round 13
// speedup vs baseline: 45.4770x; 1.2193x over previous
#include <cuda_runtime.h>
#include <cuda_bf16.h>

#define SEQ   4096
#define EMBED 256
#define NQ    8
#define TAGS  50
#define DIN   264   // EMBED + NQ
#define CHUNK  8    // timesteps owned per scan block
#define WARM   32   // warmup steps (hard bound 0.731^32 ~ 4e-5; measured ~1e-8)

// Scratch (device globals — no dynamic allocation allowed)
__device__ float4 g_Wt4[64 * 32];  // [j4][outi] transposed input weights, float4 over j
__device__ float  g_bias[32];      // [outi] gate biases
__device__ float  g_ax[SEQ * 32];  // [t][gate][q] pre-activations from x_t (+bias)

// ---------------------------------------------------------------------------
// Kernel 0: transpose input weights into [j4][outi] float4 layout + bias vec.
// Tiny one-shot: 2048 float4 elements.
// ---------------------------------------------------------------------------
__global__ void __launch_bounds__(256) transpose_kernel(
        const float* __restrict__ Wf, const float* __restrict__ bf,
        const float* __restrict__ Wi, const float* __restrict__ bi,
        const float* __restrict__ Wu, const float* __restrict__ bu,
        const float* __restrict__ Wo, const float* __restrict__ bo) {
    const int tid = threadIdx.x;
#pragma unroll
    for (int r = 0; r < 8; r++) {
        const int idx  = r * 256 + tid;        // 0..2047 = j4*32 + outi
        const int j4   = idx >> 5;
        const int outi = idx & 31;
        const int g    = outi >> 3;
        const int q    = outi & 7;
        const float* W = (g == 0) ? Wf : (g == 1) ? Wi : (g == 2) ? Wu : Wo;
        const float* row = W + q * DIN + j4 * 4;
        g_Wt4[idx] = make_float4(row[0], row[1], row[2], row[3]);
    }
    if (tid < 32) {
        const int g = tid >> 3, q = tid & 7;
        const float* b = (g == 0) ? bf : (g == 1) ? bi : (g == 2) ? bu : bo;
        g_bias[tid] = b[q];
    }
}

// ---------------------------------------------------------------------------
// Kernel 1: ax[t][outi] = W[outi,:256] @ emb[sentence[t]] + bias[outi]
// Warp-per-timestep, lane-per-output. No smem, no syncs, no reductions.
// ---------------------------------------------------------------------------
__global__ void __launch_bounds__(256) ax_kernel(
        const int* __restrict__ sent, const float* __restrict__ emb) {
    const int tid  = threadIdx.x;
    const int warp = tid >> 5;
    const int lane = tid & 31;
    const int t    = blockIdx.x * 8 + warp;

    const int s = sent[t];                       // warp-uniform load
    const float4* __restrict__ e4 = (const float4*)emb + (size_t)s * 64;

    float ac0 = 0.f, ac1 = 0.f, ac2 = 0.f, ac3 = 0.f;
#pragma unroll 16
    for (int j4 = 0; j4 < 64; j4++) {
        const float4 wv = g_Wt4[j4 * 32 + lane];
        const float4 xv = e4[j4];
        ac0 = fmaf(wv.x, xv.x, ac0);
        ac1 = fmaf(wv.y, xv.y, ac1);
        ac2 = fmaf(wv.z, xv.z, ac2);
        ac3 = fmaf(wv.w, xv.w, ac3);
    }
    g_ax[t * 32 + lane] = ((ac0 + ac1) + (ac2 + ac3)) + g_bias[lane];
}

// ---------------------------------------------------------------------------
// Kernel 2: fused chunked LSTM scan + tag head + log_softmax.
// 512 blocks x 1 warp; block c owns timesteps [c*CHUNK, (c+1)*CHUNK), warms
// up from max(0, c*CHUNK - WARM) starting at (0,0). Contraction-based
// chunking: measured truncation invisible at WARM=40; hard bound at WARM=32
// is 0.731^32 ~ 4e-5 << 1e-3.
// Quantum layer collapses analytically:
//   z_j = prod_{k<=j} cos^2(a_k)  (j>=1);   z_0 = prod_{k=1..7} cos^2(a_k)
// Gate activations: act = C + p*B(p^2), division-free odd polynomial.
// Output tanh(cx) keeps Pade(9) rational (cx in [-2.1, 2.1]).
// For owned steps, logits (tags lane, lane+32) + log_softmax are computed
// in-warp and written straight to out — no g_h round-trip, no 4th kernel.
// ---------------------------------------------------------------------------
__global__ void __launch_bounds__(32, 1) scan_kernel(
        const float* __restrict__ Wf, const float* __restrict__ Wi,
        const float* __restrict__ Wu, const float* __restrict__ Wo,
        const float* __restrict__ Wt, const float* __restrict__ bt,
        float* __restrict__ out) {
    const unsigned FULL = 0xffffffffu;
    const int lane = threadIdx.x;          // 0..31
    const int g = lane >> 3, q = lane & 7;
    const int base = g << 3;

    const int t0     = blockIdx.x * CHUNK;
    const int tstart = (t0 > WARM) ? (t0 - WARM) : 0;
    const int tend   = t0 + CHUNK;

    const float* W = (g == 0) ? Wf : (g == 1) ? Wi : (g == 2) ? Wu : Wo;
    float w[NQ];
#pragma unroll
    for (int k = 0; k < NQ; k++)
        w[k] = W[q * DIN + EMBED + k];     // recurrent slice W[:, 256:264]

    // tag-head rows for this lane: tags lane and lane+32
    const int tag1 = lane + 32;
    const bool v1 = (tag1 < TAGS);
    float wt0[NQ], wt1[NQ];
#pragma unroll
    for (int k = 0; k < NQ; k++) {
        wt0[k] = Wt[lane * NQ + k];
        wt1[k] = v1 ? Wt[tag1 * NQ + k] : 0.f;
    }
    const float bt0 = bt[lane];
    const float bt1 = v1 ? bt[tag1] : 0.f;

    // per-lane activation polynomial: act = C + p*(b0 + b1 u + b2 u^2 + b3 u^3 + b4 u^4)
    float C, b0, b1, b2, b3, b4;
    if (g == 2) {  // tanh gate
        C  = 0.0f;
        b0 = 1.0f;
        b1 = -0.33325783f;
        b2 =  0.13215491f;
        b3 = -0.04825764f;
        b4 =  0.01095456f;
    } else {       // sigmoid gates
        C  = 0.5f;
        b0 =  0.25f;
        b1 = -0.020833333f;       // -1/48
        b2 =  0.0020833333f;      //  1/480
        b3 = -2.1081349e-4f;      // -17/80640
        b4 =  2.1356855e-5f;      //  31/1451520
    }

    bool inc[NQ];
#pragma unroll
    for (int k = 0; k < NQ; k++)
        inc[k] = (k == 0) ? (q != 0) : ((q == 0) || (k <= q));

    float hx = 0.f, cx = 0.f;
    // 2-deep prefetch of ax
    float a0 = g_ax[tstart * 32 + lane];
    float a1 = g_ax[(tstart + 1) * 32 + lane];

#pragma unroll 2
    for (int t = tstart; t < tend; t++) {
        const float a = a0;
        a0 = a1;
        const int tn = (t + 2 < SEQ) ? (t + 2) : (SEQ - 1);
        a1 = g_ax[tn * 32 + lane];

        // ---- stage A: broadcast hx, recurrent matvec ----
        const float h0 = __shfl_sync(FULL, hx, 0);
        const float h1 = __shfl_sync(FULL, hx, 1);
        const float h2 = __shfl_sync(FULL, hx, 2);
        const float h3 = __shfl_sync(FULL, hx, 3);
        const float h4 = __shfl_sync(FULL, hx, 4);
        const float h5 = __shfl_sync(FULL, hx, 5);
        const float h6 = __shfl_sync(FULL, hx, 6);
        const float h7 = __shfl_sync(FULL, hx, 7);

        float c0 = fmaf(w[1], h1, fmaf(w[0], h0, a));
        float c1 = fmaf(w[3], h3, w[2] * h2);
        float c2 = fmaf(w[5], h5, w[4] * h4);
        float c3 = fmaf(w[7], h7, w[6] * h6);
        const float ang = (c0 + c1) + (c2 + c3);

        float cc = __cosf(ang);
        cc = cc * cc;

        // ---- stage B: gather cos^2, masked product ----
        float m[NQ];
#pragma unroll
        for (int k = 0; k < NQ; k++) {
            const float v = __shfl_sync(FULL, cc, base + k);
            m[k] = inc[k] ? v : 1.0f;
        }
        const float p = ((m[0] * m[1]) * (m[2] * m[3])) *
                        ((m[4] * m[5]) * (m[6] * m[7]));

        // ---- activation: division-free odd polynomial ----
        const float u = p * p;
        const float B = fmaf(fmaf(fmaf(fmaf(b4, u, b3), u, b2), u, b1), u, b0);
        const float act = fmaf(p, B, C);

        // ---- stage C: gather f,i,g,o for my wire ----
        const float fg = __shfl_sync(FULL, act, q);
        const float ig = __shfl_sync(FULL, act, 8 + q);
        const float gg = __shfl_sync(FULL, act, 16 + q);
        const float og = __shfl_sync(FULL, act, 24 + q);

        cx = fmaf(fg, cx, ig * gg);

        // hx = og * tanh(cx) via Pade: (og*cx*numc) * rcp(denc)
        const float tc   = cx * cx;
        const float numc = fmaf(tc + 105.f, tc, 945.f);
        const float denc = fmaf(fmaf(15.f, tc, 420.f), tc, 945.f);
        const float ocn  = (og * cx) * numc;
        hx = ocn * __fdividef(1.0f, denc);

        // ---- owned steps: fused tag head + log_softmax ----
        if (t >= t0) {
            float hh[NQ];
#pragma unroll
            for (int k = 0; k < NQ; k++)
                hh[k] = __shfl_sync(FULL, hx, k);

            float l0 = bt0, l1 = bt1;
#pragma unroll
            for (int k = 0; k < NQ; k++) {
                l0 = fmaf(wt0[k], hh[k], l0);
                l1 = fmaf(wt1[k], hh[k], l1);
            }
            if (!v1) l1 = -3.0e38f;

            float mx = fmaxf(l0, l1);
#pragma unroll
            for (int d = 16; d; d >>= 1)
                mx = fmaxf(mx, __shfl_xor_sync(FULL, mx, d));

            float se = __expf(l0 - mx) + (v1 ? __expf(l1 - mx) : 0.f);
#pragma unroll
            for (int d = 16; d; d >>= 1)
                se += __shfl_xor_sync(FULL, se, d);

            const float ls = mx + __logf(se);
            out[t * TAGS + lane] = l0 - ls;
            if (v1)
                out[t * TAGS + tag1] = l1 - ls;
        }
    }
}

// ---------------------------------------------------------------------------
extern "C" void kernel_launch(void* const* d_in, const int* in_sizes, int n_in,
                              void* d_out, int out_size) {
    const int*   sent = (const int*)  d_in[0];
    const float* emb  = (const float*)d_in[1];
    const float* Wf   = (const float*)d_in[2];
    const float* bf   = (const float*)d_in[3];
    const float* Wi   = (const float*)d_in[4];
    const float* bi   = (const float*)d_in[5];
    const float* Wu   = (const float*)d_in[6];
    const float* bu   = (const float*)d_in[7];
    const float* Wo   = (const float*)d_in[8];
    const float* bo   = (const float*)d_in[9];
    const float* Wt   = (const float*)d_in[10];
    const float* bt   = (const float*)d_in[11];
    float* out = (float*)d_out;

    transpose_kernel<<<1, 256>>>(Wf, bf, Wi, bi, Wu, bu, Wo, bo);
    ax_kernel<<<SEQ / 8, 256>>>(sent, emb);
    scan_kernel<<<SEQ / CHUNK, 32>>>(Wf, Wi, Wu, Wo, Wt, bt, out);
}